// round 11
// baseline (speedup 1.0000x reference)
#include <cuda_runtime.h>
#include <cuda_fp16.h>
#include <cstdint>

// Problem constants (shapes are fixed by the dataset)
#define Bb   2
#define Ss   256
#define Ee   64
#define HWp  1024      // H*W = 32*32
#define CHh  4
#define NHh  16        // heads per batch = (XH*YH)*CH
#define BHh  32        // Bb*NHh
#define Dd   4096      // hd*hh*ww = 16*16*16

// -------------------- scratch (device globals; no allocation) --------------------
__device__ __half g_q[(size_t)BHh * Ss * Dd];      // 64 MB
__device__ __half g_k[(size_t)BHh * Ss * Dd];      // 64 MB
__device__ __half g_v[(size_t)BHh * Ss * Dd];      // 64 MB
__device__ float  g_scores[(size_t)BHh * Ss * Ss]; // 8 MB
__device__ __half g_attn[(size_t)BHh * Ss * Ss];   // 4 MB
__device__ __half g_sa[(size_t)BHh * Ss * Dd];     // 64 MB
__device__ __half g_wqkv_hi[192 * 64];
__device__ __half g_wqkv_lo[192 * 64];
__device__ __half g_wout_hi[64 * 64];
__device__ __half g_wout_lo[64 * 64];

// -------------------- mma / ldmatrix / cp.async helpers --------------------
__device__ __forceinline__ void mma_16816(float* c, const uint32_t* a, const uint32_t* b) {
    asm volatile(
        "mma.sync.aligned.m16n8k16.row.col.f32.f16.f16.f32 "
        "{%0,%1,%2,%3},{%4,%5,%6,%7},{%8,%9},{%0,%1,%2,%3};"
        : "+f"(c[0]), "+f"(c[1]), "+f"(c[2]), "+f"(c[3])
        : "r"(a[0]), "r"(a[1]), "r"(a[2]), "r"(a[3]), "r"(b[0]), "r"(b[1]));
}

__device__ __forceinline__ void ldsm_x4(uint32_t* r, const __half* p) {
    uint32_t addr = (uint32_t)__cvta_generic_to_shared(p);
    asm volatile("ldmatrix.sync.aligned.m8n8.x4.shared.b16 {%0,%1,%2,%3}, [%4];"
                 : "=r"(r[0]), "=r"(r[1]), "=r"(r[2]), "=r"(r[3]) : "r"(addr));
}
__device__ __forceinline__ void ldsm_x4t(uint32_t* r, const __half* p) {
    uint32_t addr = (uint32_t)__cvta_generic_to_shared(p);
    asm volatile("ldmatrix.sync.aligned.m8n8.x4.trans.shared.b16 {%0,%1,%2,%3}, [%4];"
                 : "=r"(r[0]), "=r"(r[1]), "=r"(r[2]), "=r"(r[3]) : "r"(addr));
}
__device__ __forceinline__ void ldsm_x2(uint32_t* r, const __half* p) {
    uint32_t addr = (uint32_t)__cvta_generic_to_shared(p);
    asm volatile("ldmatrix.sync.aligned.m8n8.x2.shared.b16 {%0,%1}, [%2];"
                 : "=r"(r[0]), "=r"(r[1]) : "r"(addr));
}

__device__ __forceinline__ void cp16(__half* smem, const __half* gmem) {
    uint32_t s = (uint32_t)__cvta_generic_to_shared(smem);
    asm volatile("cp.async.cg.shared.global [%0], [%1], 16;" :: "r"(s), "l"(gmem));
}
__device__ __forceinline__ void cp_commit() {
    asm volatile("cp.async.commit_group;");
}
template <int N>
__device__ __forceinline__ void cp_wait() {
    asm volatile("cp.async.wait_group %0;" :: "n"(N));
}

__device__ __forceinline__ void split_f32(float v, __half& hi, __half& lo) {
    hi = __float2half_rn(v);
    lo = __float2half_rn(v - __half2float(hi));
}

// A-fragment (m16k16, row-major A) from transposed smem storage S[k][m]
#define A_TRANS_KROW(lane)  (((lane) & 7) + (((lane) >> 4) << 3))
#define A_TRANS_MOFF(lane)  ((((lane) >> 3) & 1) << 3)

// ==================================================================================
// Kernel 0: one-time hi/lo split of w_qkv and w_out
// ==================================================================================
__global__ __launch_bounds__(256) void wsplit_kernel(const float* __restrict__ w_qkv,
                                                     const float* __restrict__ w_out) {
    int tid = blockIdx.x * 256 + threadIdx.x;
    if (tid < 192 * 64) {
        __half h, l;
        split_f32(w_qkv[tid], h, l);
        g_wqkv_hi[tid] = h; g_wqkv_lo[tid] = l;
    }
    if (tid < 64 * 64) {
        __half h, l;
        split_f32(w_out[tid], h, l);
        g_wout_hi[tid] = h; g_wout_lo[tid] = l;
    }
}

// ==================================================================================
// Kernel 1: QKV projection via HMMA, 2 passes (X at fp16, W hi/lo), 2 CTAs/SM
//   q = Xhi*Whi + Xhi*Wlo   (omits Xlo*W ~ 2^-12 rel; output is fp16-rounded anyway)
//   grid: (B*S, 8)  block: 256 (8 warps = 2m x 4n, warp tile 64x48)
// ==================================================================================
#define XST 136   // X smem row stride (halves): 128 + 8 pad
#define WST 72    // W smem row stride (halves): 64 + 8 pad
#define OST 136   // out staging stride

__global__ __launch_bounds__(256, 2) void qkv_mma_kernel(const float* __restrict__ seq) {
    extern __shared__ __half smq[];
    __half* Xhi = smq;                 // [64 e][136] (cols = p)
    __half* Whi = Xhi + 64 * XST;      // [192 o][72] (cols = e)
    __half* Wlo = Whi + 192 * WST;

    const int bs  = blockIdx.x;
    const int p0  = blockIdx.y * 128;
    const int tid = threadIdx.x, lane = tid & 31, warp = tid >> 5;
    const int wm = warp >> 2;
    const int wn = warp & 3;

    // W hi/lo via cp.async: 192 rows x 8 chunks of 16B x 2 buffers = 3072 chunks
#pragma unroll
    for (int i = 0; i < 12; i++) {
        int cid = tid + i * 256;           // 0..3071
        int c = (cid < 1536) ? cid : (cid - 1536);
        int o = c >> 3, e8 = (c & 7) * 8;
        if (cid < 1536) cp16(Whi + o * WST + e8, g_wqkv_hi + o * 64 + e8);
        else            cp16(Wlo + o * WST + e8, g_wqkv_lo + o * 64 + e8);
    }
    cp_commit();

    // X = seq[bs][e][p0..p0+127] rounded to fp16, stored [e][p]
    const float* src = seq + (size_t)bs * Ee * HWp + p0;
#pragma unroll
    for (int i = 0; i < 8; i++) {
        int cid = tid + i * 256;
        int e = cid >> 5, p4 = (cid & 31) * 4;
        float4 v = *(const float4*)(src + (size_t)e * HWp + p4);
        __half* dh = Xhi + e * XST + p4;
        dh[0] = __float2half_rn(v.x);
        dh[1] = __float2half_rn(v.y);
        dh[2] = __float2half_rn(v.z);
        dh[3] = __float2half_rn(v.w);
    }
    cp_wait<0>();
    __syncthreads();

    float acc[4][6][4];
#pragma unroll
    for (int mt = 0; mt < 4; mt++)
#pragma unroll
        for (int nt = 0; nt < 6; nt++)
#pragma unroll
            for (int c = 0; c < 4; c++) acc[mt][nt][c] = 0.f;

    const int akrow = A_TRANS_KROW(lane);
    const int amoff = A_TRANS_MOFF(lane);
    const int bnrow = lane & 7;
    const int bkoff = ((lane >> 3) & 1) * 8;
    const int bpsel = (lane >> 4) & 1;    // pair-row select for merged ldsm_x4

#pragma unroll
    for (int ks = 0; ks < 4; ks++) {
        uint32_t a[4][4];
#pragma unroll
        for (int mt = 0; mt < 4; mt++)
            ldsm_x4t(a[mt], Xhi + (ks * 16 + akrow) * XST
                               + wm * 64 + mt * 16 + amoff);
#pragma unroll
        for (int pass = 0; pass < 2; pass++) {
            const __half* Wp = pass ? Wlo : Whi;
            uint32_t b[6][2];
#pragma unroll
            for (int np = 0; np < 6; np += 2) {
                uint32_t r4[4];
                ldsm_x4(r4, Wp + (wn * 48 + (np + bpsel) * 8 + bnrow) * WST
                              + ks * 16 + bkoff);
                b[np][0] = r4[0]; b[np][1] = r4[1];
                b[np + 1][0] = r4[2]; b[np + 1][1] = r4[3];
            }
#pragma unroll
            for (int mt = 0; mt < 4; mt++)
#pragma unroll
                for (int nt = 0; nt < 6; nt++)
                    mma_16816(acc[mt][nt], a[mt], b[nt]);
        }
    }

    __syncthreads();
    __half* OutS = smq;                    // [192][OST]
#pragma unroll
    for (int mt = 0; mt < 4; mt++) {
        int r0 = wm * 64 + mt * 16 + (lane >> 2);
#pragma unroll
        for (int nt = 0; nt < 6; nt++) {
            int ob = wn * 48 + nt * 8 + (lane & 3) * 2;
#pragma unroll
            for (int c = 0; c < 4; c++) {
                int o  = ob + (c & 1);
                int pl = r0 + (c >> 1) * 8;
                OutS[o * OST + pl] = __float2half(acc[mt][nt][c]);
            }
        }
    }
    __syncthreads();

    const int b = bs >> 8, s = bs & 255;
    const int h_base = blockIdx.y * 4;
#pragma unroll
    for (int it = 0; it < 6; it++) {
        int seg = tid + it * 256;
        int o   = seg >> 3;
        int sub = seg & 7;
        int hl  = sub >> 1;
        int sy  = sub & 1;
        int h   = h_base + hl;
        int sx = h >> 4, ii = h & 15;
        int sp = o >> 6, ch = (o >> 4) & 3, dc = o & 15;
        int head = (sx * 2 + sy) * 4 + ch;
        __half* dst = (sp == 0) ? g_q : (sp == 1) ? g_k : g_v;
        size_t di = ((size_t)(b * NHh + head) * Ss + s) * Dd + dc * 256 + ii * 16;
        const uint4* sp4 = (const uint4*)(OutS + o * OST + hl * 32 + sy * 16);
        *(uint4*)(dst + di)     = sp4[0];
        *(uint4*)(dst + di + 8) = sp4[1];
    }
}

// ==================================================================================
// Kernel 2: scores = Q @ K^T via HMMA, 64x64 tiles, cp.async 2-stage pipeline
//   grid: (BH, 4, 4)  block: 128 (4 warps, 2m x 2n, warp tile 32x32)
//   K-side fragments via merged ldsm_x4 (r9-proven mapping)
// ==================================================================================
__global__ __launch_bounds__(128) void scores_mma_kernel() {
    __shared__ __align__(16) __half Qs[2][64 * 64];
    __shared__ __align__(16) __half Ks[2][64 * 64];

    const int bh = blockIdx.x;
    const int m0 = blockIdx.y * 64;
    const int n0 = blockIdx.z * 64;
    const int tid = threadIdx.x, lane = tid & 31, warp = tid >> 5;
    const int wm = warp >> 1;   // 0..1
    const int wn = warp & 1;    // 0..1

    const __half* qb = g_q + (size_t)bh * Ss * Dd;
    const __half* kb = g_k + (size_t)bh * Ss * Dd;

    float acc[2][4][4];
#pragma unroll
    for (int mt = 0; mt < 2; mt++)
#pragma unroll
        for (int nt = 0; nt < 4; nt++)
#pragma unroll
            for (int c = 0; c < 4; c++) acc[mt][nt][c] = 0.f;

    auto issue_loads = [&](int buf, int kk) {
#pragma unroll
        for (int i = 0; i < 4; i++) {
            int cid = tid + i * 128;          // 0..511
            int row = cid >> 3, c8 = cid & 7;
            int sw = (c8 ^ (row & 7)) << 3;
            cp16(Qs[buf] + row * 64 + sw, qb + (size_t)(m0 + row) * Dd + kk + c8 * 8);
            cp16(Ks[buf] + row * 64 + sw, kb + (size_t)(n0 + row) * Dd + kk + c8 * 8);
        }
        cp_commit();
    };

    issue_loads(0, 0);
    const int T = Dd / 64;   // 64
    for (int t = 0; t < T; t++) {
        if (t + 1 < T) {
            issue_loads((t + 1) & 1, (t + 1) * 64);
            cp_wait<1>();
        } else {
            cp_wait<0>();
        }
        __syncthreads();

        const __half* Qb = Qs[t & 1];
        const __half* Kb = Ks[t & 1];
#pragma unroll
        for (int ks = 0; ks < 4; ks++) {
            uint32_t a[2][4], b[4][2];
#pragma unroll
            for (int mt = 0; mt < 2; mt++) {
                int row = wm * 32 + mt * 16 + (lane & 15);
                int chk = ks * 2 + (lane >> 4);
                ldsm_x4(a[mt], Qb + row * 64 + ((chk ^ (row & 7)) << 3));
            }
#pragma unroll
            for (int np = 0; np < 4; np += 2) {
                uint32_t r4[4];
                int row = wn * 32 + (np + ((lane >> 4) & 1)) * 8 + (lane & 7);
                int chk = ks * 2 + ((lane >> 3) & 1);
                ldsm_x4(r4, Kb + row * 64 + ((chk ^ (row & 7)) << 3));
                b[np][0] = r4[0]; b[np][1] = r4[1];
                b[np + 1][0] = r4[2]; b[np + 1][1] = r4[3];
            }
#pragma unroll
            for (int mt = 0; mt < 2; mt++)
#pragma unroll
                for (int nt = 0; nt < 4; nt++)
                    mma_16816(acc[mt][nt], a[mt], b[nt]);
        }
        __syncthreads();
    }

#pragma unroll
    for (int mt = 0; mt < 2; mt++) {
#pragma unroll
        for (int nt = 0; nt < 4; nt++) {
            int r = m0 + wm * 32 + mt * 16 + (lane >> 2);
            int c = n0 + wn * 32 + nt * 8 + (lane & 3) * 2;
            float* dst = g_scores + ((size_t)bh * Ss + r) * Ss + c;
            dst[0] = acc[mt][nt][0];
            dst[1] = acc[mt][nt][1];
            dst[8 * Ss + 0] = acc[mt][nt][2];
            dst[8 * Ss + 1] = acc[mt][nt][3];
        }
    }
}

// ==================================================================================
// Kernel 3: softmax per row, faithful fp16 rounding at each op boundary
// ==================================================================================
__global__ __launch_bounds__(256) void softmax_kernel() {
    const int row  = blockIdx.x * 8 + (threadIdx.x >> 5);
    const int lane = threadIdx.x & 31;

    const float* srow = g_scores + (size_t)row * Ss;
    __half* arow = g_attn + (size_t)row * Ss;

    float l[8];
    float m = -1e30f;
#pragma unroll
    for (int i = 0; i < 8; i++) {
        float v = __half2float(__float2half(srow[lane + 32 * i])) * 0.015625f;
        l[i] = v;
        m = fmaxf(m, v);
    }
#pragma unroll
    for (int o = 16; o > 0; o >>= 1) m = fmaxf(m, __shfl_xor_sync(0xffffffffu, m, o));

    float e[8];
    float sum = 0.f;
#pragma unroll
    for (int i = 0; i < 8; i++) {
        float t = __half2float(__float2half(l[i] - m));
        e[i] = __half2float(__float2half(expf(t)));
        sum += e[i];
    }
#pragma unroll
    for (int o = 16; o > 0; o >>= 1) sum += __shfl_xor_sync(0xffffffffu, sum, o);

#pragma unroll
    for (int i = 0; i < 8; i++)
        arow[lane + 32 * i] = __float2half(e[i] / sum);
}

// ==================================================================================
// Kernel 4: SA = attn @ V via HMMA, cp.async 2-stage, 2 CTAs/SM
//   grid: (BH, 2, 32)  block: 256 (8 warps, 2m x 4n, warp tile 64x32)
// ==================================================================================
__global__ __launch_bounds__(256, 2) void av_mma_kernel() {
    extern __shared__ __half sma[];
    __half* As = sma;                    // [2][128*64]
    __half* Vs = sma + 2 * 128 * 64;     // [2][64*128]

    const int bh = blockIdx.x;
    const int m0 = blockIdx.y * 128;
    const int n0 = blockIdx.z * 128;
    const int tid = threadIdx.x, lane = tid & 31, warp = tid >> 5;
    const int wm = warp & 1;
    const int wn = warp >> 1;

    const __half* ab = g_attn + (size_t)bh * Ss * Ss;
    const __half* vb = g_v + (size_t)bh * Ss * Dd;

    float acc[4][4][4];
#pragma unroll
    for (int mt = 0; mt < 4; mt++)
#pragma unroll
        for (int nt = 0; nt < 4; nt++)
#pragma unroll
            for (int c = 0; c < 4; c++) acc[mt][nt][c] = 0.f;

    auto issue_loads = [&](int buf, int kk) {
        __half* Ab = As + buf * 128 * 64;
        __half* Vb = Vs + buf * 64 * 128;
#pragma unroll
        for (int i = 0; i < 4; i++) {
            int cid = tid + i * 256;
            int row = cid >> 3, c8 = cid & 7;
            int sw = (c8 ^ (row & 7)) << 3;
            cp16(Ab + row * 64 + sw, ab + (size_t)(m0 + row) * Ss + kk + c8 * 8);
        }
#pragma unroll
        for (int i = 0; i < 4; i++) {
            int cid = tid + i * 256;
            int row = cid >> 4, c = cid & 15;
            int sw = (c ^ (row & 7)) << 3;
            cp16(Vb + row * 128 + sw, vb + (size_t)(kk + row) * Dd + n0 + c * 8);
        }
        cp_commit();
    };

    issue_loads(0, 0);
    const int T = Ss / 64;   // 4
    for (int t = 0; t < T; t++) {
        if (t + 1 < T) {
            issue_loads((t + 1) & 1, (t + 1) * 64);
            cp_wait<1>();
        } else {
            cp_wait<0>();
        }
        __syncthreads();

        const __half* Ab = As + (t & 1) * 128 * 64;
        const __half* Vb = Vs + (t & 1) * 64 * 128;
#pragma unroll
        for (int ks = 0; ks < 4; ks++) {
            uint32_t a[4][4], b[4][2];
#pragma unroll
            for (int mt = 0; mt < 4; mt++) {
                int row = wm * 64 + mt * 16 + (lane & 15);
                int chk = ks * 2 + (lane >> 4);
                ldsm_x4(a[mt], Ab + row * 64 + ((chk ^ (row & 7)) << 3));
            }
#pragma unroll
            for (int np = 0; np < 4; np += 2) {
                uint32_t r4[4];
                int row = ks * 16 + (lane & 15);
                int chk = wn * 4 + np + (lane >> 4);
                ldsm_x4t(r4, Vb + row * 128 + ((chk ^ (row & 7)) << 3));
                b[np][0] = r4[0]; b[np][1] = r4[1];
                b[np + 1][0] = r4[2]; b[np + 1][1] = r4[3];
            }
#pragma unroll
            for (int mt = 0; mt < 4; mt++)
#pragma unroll
                for (int nt = 0; nt < 4; nt++)
                    mma_16816(acc[mt][nt], a[mt], b[nt]);
        }
        __syncthreads();
    }

#pragma unroll
    for (int mt = 0; mt < 4; mt++) {
#pragma unroll
        for (int nt = 0; nt < 4; nt++) {
            int r = m0 + wm * 64 + mt * 16 + (lane >> 2);
            int c = n0 + wn * 32 + nt * 8 + (lane & 3) * 2;
            __half* dst = g_sa + ((size_t)bh * Ss + r) * Dd + c;
            *(__half2*)dst = __floats2half2_rn(acc[mt][nt][0], acc[mt][nt][1]);
            *(__half2*)(dst + 8 * Dd) = __floats2half2_rn(acc[mt][nt][2], acc[mt][nt][3]);
        }
    }
}

// ==================================================================================
// Kernel 5: recompose2d gather + output projection via HMMA (2-pass w hi/lo)
// ==================================================================================
__global__ __launch_bounds__(256) void out_mma_kernel(const float* __restrict__ b_out,
                                                      float* __restrict__ out) {
    __shared__ __align__(16) __half Ah[64 * XST];
    __shared__ __align__(16) __half Whi2[64 * WST];
    __shared__ __align__(16) __half Wlo2[64 * WST];

    const int bs  = blockIdx.x;
    const int p0  = blockIdx.y * 128;
    const int tid = threadIdx.x, lane = tid & 31, warp = tid >> 5;
    const int wm = warp >> 1;
    const int wn = warp & 1;
    const int b = bs >> 8, s = bs & 255;

    // W hi/lo via cp.async: 64 rows x 8 chunks x 2 buffers = 1024 chunks
#pragma unroll
    for (int i = 0; i < 4; i++) {
        int cid = tid + i * 256;           // 0..1023
        int c = cid & 511;
        int o = c >> 3, e8 = (c & 7) * 8;
        if (cid < 512) cp16(Whi2 + o * WST + e8, g_wout_hi + o * 64 + e8);
        else           cp16(Wlo2 + o * WST + e8, g_wout_lo + o * 64 + e8);
    }
    cp_commit();

    // gather SA (recompose2d) into [c][p], vectorized 8-half runs
#pragma unroll
    for (int i = 0; i < 4; i++) {
        int cid = tid + i * 256;           // 0..1023
        int c = cid >> 4, run = cid & 15;
        int p = run * 8;
        int pg = p0 + p;
        int h = pg >> 5, w0 = pg & 31;
        int head = ((h >> 4) * 2 + (w0 >> 4)) * 4 + (c >> 4);
        int d = (c & 15) * 256 + (h & 15) * 16 + (w0 & 15);
        *(uint4*)(Ah + c * XST + p) =
            *(const uint4*)(g_sa + ((size_t)(b * NHh + head) * Ss + s) * Dd + d);
    }
    cp_wait<0>();
    __syncthreads();

    float acc[2][4][4];
#pragma unroll
    for (int mt = 0; mt < 2; mt++)
#pragma unroll
        for (int nt = 0; nt < 4; nt++)
#pragma unroll
            for (int c = 0; c < 4; c++) acc[mt][nt][c] = 0.f;

    const int akrow = A_TRANS_KROW(lane);
    const int amoff = A_TRANS_MOFF(lane);
    const int bnrow = lane & 7;
    const int bkoff = ((lane >> 3) & 1) * 8;

#pragma unroll
    for (int pass = 0; pass < 2; pass++) {
        const __half* Wp = pass ? Wlo2 : Whi2;
#pragma unroll
        for (int ks = 0; ks < 4; ks++) {
            uint32_t a[2][4], bfr[4][2];
#pragma unroll
            for (int mt = 0; mt < 2; mt++)
                ldsm_x4t(a[mt], Ah + (ks * 16 + akrow) * XST
                                   + wm * 32 + mt * 16 + amoff);
#pragma unroll
            for (int nt = 0; nt < 4; nt++)
                ldsm_x2(bfr[nt], Wp + (wn * 32 + nt * 8 + bnrow) * WST
                                    + ks * 16 + bkoff);
#pragma unroll
            for (int mt = 0; mt < 2; mt++)
#pragma unroll
                for (int nt = 0; nt < 4; nt++)
                    mma_16816(acc[mt][nt], a[mt], bfr[nt]);
        }
    }

#pragma unroll
    for (int mt = 0; mt < 2; mt++) {
        int r0 = wm * 32 + mt * 16 + (lane >> 2);
#pragma unroll
        for (int nt = 0; nt < 4; nt++) {
            int ob = wn * 32 + nt * 8 + (lane & 3) * 2;
#pragma unroll
            for (int c = 0; c < 4; c++) {
                int o  = ob + (c & 1);
                int rr = r0 + (c >> 1) * 8;
                out[((size_t)bs * 64 + o) * HWp + p0 + rr] = acc[mt][nt][c] + b_out[o];
            }
        }
    }
}

// ==================================================================================
extern "C" void kernel_launch(void* const* d_in, const int* in_sizes, int n_in,
                              void* d_out, int out_size) {
    const float* seq   = (const float*)d_in[0];
    const float* w_qkv = (const float*)d_in[1];
    const float* w_out = (const float*)d_in[2];
    const float* b_out = (const float*)d_in[3];
    float* out = (float*)d_out;

    const int qkv_smem = (64 * XST + 2 * 192 * WST) * (int)sizeof(__half);
    cudaFuncSetAttribute(qkv_mma_kernel, cudaFuncAttributeMaxDynamicSharedMemorySize,
                         qkv_smem);
    cudaFuncSetAttribute(qkv_mma_kernel, cudaFuncAttributePreferredSharedMemoryCarveout,
                         100);
    const int av_smem = (2 * 128 * 64 + 2 * 64 * 128) * (int)sizeof(__half);
    cudaFuncSetAttribute(av_mma_kernel, cudaFuncAttributeMaxDynamicSharedMemorySize,
                         av_smem);
    cudaFuncSetAttribute(av_mma_kernel, cudaFuncAttributePreferredSharedMemoryCarveout,
                         100);

    wsplit_kernel<<<48, 256>>>(w_qkv, w_out);

    dim3 g1(Bb * Ss, 8);
    qkv_mma_kernel<<<g1, 256, qkv_smem>>>(seq);

    dim3 g2(BHh, 4, 4);
    scores_mma_kernel<<<g2, 128>>>();

    softmax_kernel<<<BHh * Ss / 8, 256>>>();

    dim3 g4(BHh, 2, 32);
    av_mma_kernel<<<g4, 256, av_smem>>>();

    dim3 g5(Bb * Ss, 8);
    out_mma_kernel<<<g5, 256>>>(b_out, out);
}

// round 12
// speedup vs baseline: 1.0993x; 1.0993x over previous
#include <cuda_runtime.h>
#include <cuda_fp16.h>
#include <cstdint>

// Problem constants (shapes are fixed by the dataset)
#define Bb   2
#define Ss   256
#define Ee   64
#define HWp  1024      // H*W = 32*32
#define CHh  4
#define NHh  16        // heads per batch = (XH*YH)*CH
#define BHh  32        // Bb*NHh
#define Dd   4096      // hd*hh*ww = 16*16*16

// -------------------- scratch (device globals; no allocation) --------------------
__device__ __half g_q[(size_t)BHh * Ss * Dd];      // 64 MB
__device__ __half g_k[(size_t)BHh * Ss * Dd];      // 64 MB
__device__ __half g_v[(size_t)BHh * Ss * Dd];      // 64 MB
__device__ float  g_scores[(size_t)BHh * Ss * Ss]; // 8 MB
__device__ __half g_attn[(size_t)BHh * Ss * Ss];   // 4 MB
__device__ __half g_sa[(size_t)BHh * Ss * Dd];     // 64 MB
__device__ __half g_wqkv_hi[192 * 64];
__device__ __half g_wqkv_lo[192 * 64];
__device__ __half g_wout_hi[64 * 64];
__device__ __half g_wout_lo[64 * 64];

// -------------------- mma / ldmatrix / cp.async helpers --------------------
__device__ __forceinline__ void mma_16816(float* c, const uint32_t* a, const uint32_t* b) {
    asm volatile(
        "mma.sync.aligned.m16n8k16.row.col.f32.f16.f16.f32 "
        "{%0,%1,%2,%3},{%4,%5,%6,%7},{%8,%9},{%0,%1,%2,%3};"
        : "+f"(c[0]), "+f"(c[1]), "+f"(c[2]), "+f"(c[3])
        : "r"(a[0]), "r"(a[1]), "r"(a[2]), "r"(a[3]), "r"(b[0]), "r"(b[1]));
}

__device__ __forceinline__ void ldsm_x4(uint32_t* r, const __half* p) {
    uint32_t addr = (uint32_t)__cvta_generic_to_shared(p);
    asm volatile("ldmatrix.sync.aligned.m8n8.x4.shared.b16 {%0,%1,%2,%3}, [%4];"
                 : "=r"(r[0]), "=r"(r[1]), "=r"(r[2]), "=r"(r[3]) : "r"(addr));
}
__device__ __forceinline__ void ldsm_x4t(uint32_t* r, const __half* p) {
    uint32_t addr = (uint32_t)__cvta_generic_to_shared(p);
    asm volatile("ldmatrix.sync.aligned.m8n8.x4.trans.shared.b16 {%0,%1,%2,%3}, [%4];"
                 : "=r"(r[0]), "=r"(r[1]), "=r"(r[2]), "=r"(r[3]) : "r"(addr));
}
__device__ __forceinline__ void ldsm_x2(uint32_t* r, const __half* p) {
    uint32_t addr = (uint32_t)__cvta_generic_to_shared(p);
    asm volatile("ldmatrix.sync.aligned.m8n8.x2.shared.b16 {%0,%1}, [%2];"
                 : "=r"(r[0]), "=r"(r[1]) : "r"(addr));
}

__device__ __forceinline__ void cp16(__half* smem, const __half* gmem) {
    uint32_t s = (uint32_t)__cvta_generic_to_shared(smem);
    asm volatile("cp.async.cg.shared.global [%0], [%1], 16;" :: "r"(s), "l"(gmem));
}
__device__ __forceinline__ void cp_commit() {
    asm volatile("cp.async.commit_group;");
}
template <int N>
__device__ __forceinline__ void cp_wait() {
    asm volatile("cp.async.wait_group %0;" :: "n"(N));
}

__device__ __forceinline__ void split_f32(float v, __half& hi, __half& lo) {
    hi = __float2half_rn(v);
    lo = __float2half_rn(v - __half2float(hi));
}

// A-fragment (m16k16, row-major A) from transposed smem storage S[k][m]
#define A_TRANS_KROW(lane)  (((lane) & 7) + (((lane) >> 4) << 3))
#define A_TRANS_MOFF(lane)  ((((lane) >> 3) & 1) << 3)

// ==================================================================================
// Kernel 0: one-time hi/lo split of w_qkv and w_out
// ==================================================================================
__global__ __launch_bounds__(256) void wsplit_kernel(const float* __restrict__ w_qkv,
                                                     const float* __restrict__ w_out) {
    int tid = blockIdx.x * 256 + threadIdx.x;
    if (tid < 192 * 64) {
        __half h, l;
        split_f32(w_qkv[tid], h, l);
        g_wqkv_hi[tid] = h; g_wqkv_lo[tid] = l;
    }
    if (tid < 64 * 64) {
        __half h, l;
        split_f32(w_out[tid], h, l);
        g_wout_hi[tid] = h; g_wout_lo[tid] = l;
    }
}

// ==================================================================================
// Kernel 1: QKV projection via HMMA with fp16 hi/lo split (3 passes), 2 CTAs/SM
//   (round-10 form restored: the 3rd (Xlo) pass is numerics-load-bearing)
//   grid: (B*S, 8)  block: 256 (8 warps = 2m x 4n, warp tile 64x48)
// ==================================================================================
#define XST 136   // X smem row stride (halves): 128 + 8 pad
#define WST 72    // W smem row stride (halves): 64 + 8 pad
#define OST 136   // out staging stride

__global__ __launch_bounds__(256, 2) void qkv_mma_kernel(const float* __restrict__ seq) {
    extern __shared__ __half smq[];
    __half* Xhi = smq;                 // [64 e][136] (cols = p)
    __half* Xlo = Xhi + 64 * XST;
    __half* Whi = Xlo + 64 * XST;      // [192 o][72] (cols = e)
    __half* Wlo = Whi + 192 * WST;

    const int bs  = blockIdx.x;
    const int p0  = blockIdx.y * 128;
    const int tid = threadIdx.x, lane = tid & 31, warp = tid >> 5;
    const int wm = warp >> 2;
    const int wn = warp & 3;

    // W hi/lo via cp.async: 192 rows x 8 chunks of 16B x 2 buffers = 3072 chunks
#pragma unroll
    for (int i = 0; i < 12; i++) {
        int cid = tid + i * 256;           // 0..3071
        int c = (cid < 1536) ? cid : (cid - 1536);
        int o = c >> 3, e8 = (c & 7) * 8;
        if (cid < 1536) cp16(Whi + o * WST + e8, g_wqkv_hi + o * 64 + e8);
        else            cp16(Wlo + o * WST + e8, g_wqkv_lo + o * 64 + e8);
    }
    cp_commit();

    // X = seq[bs][e][p0..p0+127], split into hi/lo, store [e][p]
    const float* src = seq + (size_t)bs * Ee * HWp + p0;
#pragma unroll
    for (int i = 0; i < 8; i++) {
        int cid = tid + i * 256;
        int e = cid >> 5, p4 = (cid & 31) * 4;
        float4 v = *(const float4*)(src + (size_t)e * HWp + p4);
        __half h0, l0, h1, l1, h2, l2, h3, l3;
        split_f32(v.x, h0, l0); split_f32(v.y, h1, l1);
        split_f32(v.z, h2, l2); split_f32(v.w, h3, l3);
        __half* dh = Xhi + e * XST + p4;
        dh[0] = h0; dh[1] = h1; dh[2] = h2; dh[3] = h3;
        __half* dl = Xlo + e * XST + p4;
        dl[0] = l0; dl[1] = l1; dl[2] = l2; dl[3] = l3;
    }
    cp_wait<0>();
    __syncthreads();

    float acc[4][6][4];
#pragma unroll
    for (int mt = 0; mt < 4; mt++)
#pragma unroll
        for (int nt = 0; nt < 6; nt++)
#pragma unroll
            for (int c = 0; c < 4; c++) acc[mt][nt][c] = 0.f;

    const int akrow = A_TRANS_KROW(lane);
    const int amoff = A_TRANS_MOFF(lane);
    const int bnrow = lane & 7;
    const int bkoff = ((lane >> 3) & 1) * 8;

#pragma unroll
    for (int pass = 0; pass < 3; pass++) {
        const __half* Xp = (pass == 2) ? Xlo : Xhi;
        const __half* Wp = (pass == 1) ? Wlo : Whi;
#pragma unroll
        for (int ks = 0; ks < 4; ks++) {
            uint32_t a[4][4], b[6][2];
#pragma unroll
            for (int mt = 0; mt < 4; mt++)
                ldsm_x4t(a[mt], Xp + (ks * 16 + akrow) * XST
                                   + wm * 64 + mt * 16 + amoff);
#pragma unroll
            for (int nt = 0; nt < 6; nt++)
                ldsm_x2(b[nt], Wp + (wn * 48 + nt * 8 + bnrow) * WST
                                  + ks * 16 + bkoff);
#pragma unroll
            for (int mt = 0; mt < 4; mt++)
#pragma unroll
                for (int nt = 0; nt < 6; nt++)
                    mma_16816(acc[mt][nt], a[mt], b[nt]);
        }
    }

    __syncthreads();
    __half* OutS = smq;                    // [192][OST]
#pragma unroll
    for (int mt = 0; mt < 4; mt++) {
        int r0 = wm * 64 + mt * 16 + (lane >> 2);
#pragma unroll
        for (int nt = 0; nt < 6; nt++) {
            int ob = wn * 48 + nt * 8 + (lane & 3) * 2;
#pragma unroll
            for (int c = 0; c < 4; c++) {
                int o  = ob + (c & 1);
                int pl = r0 + (c >> 1) * 8;
                OutS[o * OST + pl] = __float2half(acc[mt][nt][c]);
            }
        }
    }
    __syncthreads();

    const int b = bs >> 8, s = bs & 255;
    const int h_base = blockIdx.y * 4;
#pragma unroll
    for (int it = 0; it < 6; it++) {
        int seg = tid + it * 256;
        int o   = seg >> 3;
        int sub = seg & 7;
        int hl  = sub >> 1;
        int sy  = sub & 1;
        int h   = h_base + hl;
        int sx = h >> 4, ii = h & 15;
        int sp = o >> 6, ch = (o >> 4) & 3, dc = o & 15;
        int head = (sx * 2 + sy) * 4 + ch;
        __half* dst = (sp == 0) ? g_q : (sp == 1) ? g_k : g_v;
        size_t di = ((size_t)(b * NHh + head) * Ss + s) * Dd + dc * 256 + ii * 16;
        const uint4* sp4 = (const uint4*)(OutS + o * OST + hl * 32 + sy * 16);
        *(uint4*)(dst + di)     = sp4[0];
        *(uint4*)(dst + di + 8) = sp4[1];
    }
}

// ==================================================================================
// Kernel 2: scores = Q @ K^T via HMMA, 64x64 tiles, cp.async 2-stage pipeline
//   grid: (BH, 4, 4)  block: 128 (4 warps, 2m x 2n, warp tile 32x32)
//   K-side fragments via merged ldsm_x4 (pure load reorg, bit-identical output)
// ==================================================================================
__global__ __launch_bounds__(128) void scores_mma_kernel() {
    __shared__ __align__(16) __half Qs[2][64 * 64];
    __shared__ __align__(16) __half Ks[2][64 * 64];

    const int bh = blockIdx.x;
    const int m0 = blockIdx.y * 64;
    const int n0 = blockIdx.z * 64;
    const int tid = threadIdx.x, lane = tid & 31, warp = tid >> 5;
    const int wm = warp >> 1;   // 0..1
    const int wn = warp & 1;    // 0..1

    const __half* qb = g_q + (size_t)bh * Ss * Dd;
    const __half* kb = g_k + (size_t)bh * Ss * Dd;

    float acc[2][4][4];
#pragma unroll
    for (int mt = 0; mt < 2; mt++)
#pragma unroll
        for (int nt = 0; nt < 4; nt++)
#pragma unroll
            for (int c = 0; c < 4; c++) acc[mt][nt][c] = 0.f;

    auto issue_loads = [&](int buf, int kk) {
#pragma unroll
        for (int i = 0; i < 4; i++) {
            int cid = tid + i * 128;          // 0..511
            int row = cid >> 3, c8 = cid & 7;
            int sw = (c8 ^ (row & 7)) << 3;
            cp16(Qs[buf] + row * 64 + sw, qb + (size_t)(m0 + row) * Dd + kk + c8 * 8);
            cp16(Ks[buf] + row * 64 + sw, kb + (size_t)(n0 + row) * Dd + kk + c8 * 8);
        }
        cp_commit();
    };

    issue_loads(0, 0);
    const int T = Dd / 64;   // 64
    for (int t = 0; t < T; t++) {
        if (t + 1 < T) {
            issue_loads((t + 1) & 1, (t + 1) * 64);
            cp_wait<1>();
        } else {
            cp_wait<0>();
        }
        __syncthreads();

        const __half* Qb = Qs[t & 1];
        const __half* Kb = Ks[t & 1];
#pragma unroll
        for (int ks = 0; ks < 4; ks++) {
            uint32_t a[2][4], b[4][2];
#pragma unroll
            for (int mt = 0; mt < 2; mt++) {
                int row = wm * 32 + mt * 16 + (lane & 15);
                int chk = ks * 2 + (lane >> 4);
                ldsm_x4(a[mt], Qb + row * 64 + ((chk ^ (row & 7)) << 3));
            }
#pragma unroll
            for (int np = 0; np < 4; np += 2) {
                uint32_t r4[4];
                int row = wn * 32 + (np + ((lane >> 4) & 1)) * 8 + (lane & 7);
                int chk = ks * 2 + ((lane >> 3) & 1);
                ldsm_x4(r4, Kb + row * 64 + ((chk ^ (row & 7)) << 3));
                b[np][0] = r4[0]; b[np][1] = r4[1];
                b[np + 1][0] = r4[2]; b[np + 1][1] = r4[3];
            }
#pragma unroll
            for (int mt = 0; mt < 2; mt++)
#pragma unroll
                for (int nt = 0; nt < 4; nt++)
                    mma_16816(acc[mt][nt], a[mt], b[nt]);
        }
        __syncthreads();
    }

#pragma unroll
    for (int mt = 0; mt < 2; mt++) {
#pragma unroll
        for (int nt = 0; nt < 4; nt++) {
            int r = m0 + wm * 32 + mt * 16 + (lane >> 2);
            int c = n0 + wn * 32 + nt * 8 + (lane & 3) * 2;
            float* dst = g_scores + ((size_t)bh * Ss + r) * Ss + c;
            dst[0] = acc[mt][nt][0];
            dst[1] = acc[mt][nt][1];
            dst[8 * Ss + 0] = acc[mt][nt][2];
            dst[8 * Ss + 1] = acc[mt][nt][3];
        }
    }
}

// ==================================================================================
// Kernel 3: softmax per row, faithful fp16 rounding at each op boundary
// ==================================================================================
__global__ __launch_bounds__(256) void softmax_kernel() {
    const int row  = blockIdx.x * 8 + (threadIdx.x >> 5);
    const int lane = threadIdx.x & 31;

    const float* srow = g_scores + (size_t)row * Ss;
    __half* arow = g_attn + (size_t)row * Ss;

    float l[8];
    float m = -1e30f;
#pragma unroll
    for (int i = 0; i < 8; i++) {
        float v = __half2float(__float2half(srow[lane + 32 * i])) * 0.015625f;
        l[i] = v;
        m = fmaxf(m, v);
    }
#pragma unroll
    for (int o = 16; o > 0; o >>= 1) m = fmaxf(m, __shfl_xor_sync(0xffffffffu, m, o));

    float e[8];
    float sum = 0.f;
#pragma unroll
    for (int i = 0; i < 8; i++) {
        float t = __half2float(__float2half(l[i] - m));
        e[i] = __half2float(__float2half(expf(t)));
        sum += e[i];
    }
#pragma unroll
    for (int o = 16; o > 0; o >>= 1) sum += __shfl_xor_sync(0xffffffffu, sum, o);

#pragma unroll
    for (int i = 0; i < 8; i++)
        arow[lane + 32 * i] = __float2half(e[i] / sum);
}

// ==================================================================================
// Kernel 4: SA = attn @ V via HMMA, cp.async 2-stage, 2 CTAs/SM
//   grid: (BH, 2, 32)  block: 256 (8 warps, 2m x 4n, warp tile 64x32)
// ==================================================================================
__global__ __launch_bounds__(256, 2) void av_mma_kernel() {
    extern __shared__ __half sma[];
    __half* As = sma;                    // [2][128*64]
    __half* Vs = sma + 2 * 128 * 64;     // [2][64*128]

    const int bh = blockIdx.x;
    const int m0 = blockIdx.y * 128;
    const int n0 = blockIdx.z * 128;
    const int tid = threadIdx.x, lane = tid & 31, warp = tid >> 5;
    const int wm = warp & 1;
    const int wn = warp >> 1;

    const __half* ab = g_attn + (size_t)bh * Ss * Ss;
    const __half* vb = g_v + (size_t)bh * Ss * Dd;

    float acc[4][4][4];
#pragma unroll
    for (int mt = 0; mt < 4; mt++)
#pragma unroll
        for (int nt = 0; nt < 4; nt++)
#pragma unroll
            for (int c = 0; c < 4; c++) acc[mt][nt][c] = 0.f;

    auto issue_loads = [&](int buf, int kk) {
        __half* Ab = As + buf * 128 * 64;
        __half* Vb = Vs + buf * 64 * 128;
#pragma unroll
        for (int i = 0; i < 4; i++) {
            int cid = tid + i * 256;
            int row = cid >> 3, c8 = cid & 7;
            int sw = (c8 ^ (row & 7)) << 3;
            cp16(Ab + row * 64 + sw, ab + (size_t)(m0 + row) * Ss + kk + c8 * 8);
        }
#pragma unroll
        for (int i = 0; i < 4; i++) {
            int cid = tid + i * 256;
            int row = cid >> 4, c = cid & 15;
            int sw = (c ^ (row & 7)) << 3;
            cp16(Vb + row * 128 + sw, vb + (size_t)(kk + row) * Dd + n0 + c * 8);
        }
        cp_commit();
    };

    issue_loads(0, 0);
    const int T = Ss / 64;   // 4
    for (int t = 0; t < T; t++) {
        if (t + 1 < T) {
            issue_loads((t + 1) & 1, (t + 1) * 64);
            cp_wait<1>();
        } else {
            cp_wait<0>();
        }
        __syncthreads();

        const __half* Ab = As + (t & 1) * 128 * 64;
        const __half* Vb = Vs + (t & 1) * 64 * 128;
#pragma unroll
        for (int ks = 0; ks < 4; ks++) {
            uint32_t a[4][4], b[4][2];
#pragma unroll
            for (int mt = 0; mt < 4; mt++) {
                int row = wm * 64 + mt * 16 + (lane & 15);
                int chk = ks * 2 + (lane >> 4);
                ldsm_x4(a[mt], Ab + row * 64 + ((chk ^ (row & 7)) << 3));
            }
#pragma unroll
            for (int np = 0; np < 4; np += 2) {
                uint32_t r4[4];
                int row = ks * 16 + (lane & 15);
                int chk = wn * 4 + np + (lane >> 4);
                ldsm_x4t(r4, Vb + row * 128 + ((chk ^ (row & 7)) << 3));
                b[np][0] = r4[0]; b[np][1] = r4[1];
                b[np + 1][0] = r4[2]; b[np + 1][1] = r4[3];
            }
#pragma unroll
            for (int mt = 0; mt < 4; mt++)
#pragma unroll
                for (int nt = 0; nt < 4; nt++)
                    mma_16816(acc[mt][nt], a[mt], b[nt]);
        }
        __syncthreads();
    }

#pragma unroll
    for (int mt = 0; mt < 4; mt++) {
#pragma unroll
        for (int nt = 0; nt < 4; nt++) {
            int r = m0 + wm * 64 + mt * 16 + (lane >> 2);
            int c = n0 + wn * 32 + nt * 8 + (lane & 3) * 2;
            __half* dst = g_sa + ((size_t)bh * Ss + r) * Dd + c;
            *(__half2*)dst = __floats2half2_rn(acc[mt][nt][0], acc[mt][nt][1]);
            *(__half2*)(dst + 8 * Dd) = __floats2half2_rn(acc[mt][nt][2], acc[mt][nt][3]);
        }
    }
}

// ==================================================================================
// Kernel 5: recompose2d gather + output projection via HMMA (2-pass w hi/lo)
// ==================================================================================
__global__ __launch_bounds__(256) void out_mma_kernel(const float* __restrict__ b_out,
                                                      float* __restrict__ out) {
    __shared__ __align__(16) __half Ah[64 * XST];
    __shared__ __align__(16) __half Whi2[64 * WST];
    __shared__ __align__(16) __half Wlo2[64 * WST];

    const int bs  = blockIdx.x;
    const int p0  = blockIdx.y * 128;
    const int tid = threadIdx.x, lane = tid & 31, warp = tid >> 5;
    const int wm = warp >> 1;
    const int wn = warp & 1;
    const int b = bs >> 8, s = bs & 255;

    // W hi/lo via cp.async: 64 rows x 8 chunks x 2 buffers = 1024 chunks
#pragma unroll
    for (int i = 0; i < 4; i++) {
        int cid = tid + i * 256;           // 0..1023
        int c = cid & 511;
        int o = c >> 3, e8 = (c & 7) * 8;
        if (cid < 512) cp16(Whi2 + o * WST + e8, g_wout_hi + o * 64 + e8);
        else           cp16(Wlo2 + o * WST + e8, g_wout_lo + o * 64 + e8);
    }
    cp_commit();

    // gather SA (recompose2d) into [c][p], vectorized 8-half runs
#pragma unroll
    for (int i = 0; i < 4; i++) {
        int cid = tid + i * 256;           // 0..1023
        int c = cid >> 4, run = cid & 15;
        int p = run * 8;
        int pg = p0 + p;
        int h = pg >> 5, w0 = pg & 31;
        int head = ((h >> 4) * 2 + (w0 >> 4)) * 4 + (c >> 4);
        int d = (c & 15) * 256 + (h & 15) * 16 + (w0 & 15);
        *(uint4*)(Ah + c * XST + p) =
            *(const uint4*)(g_sa + ((size_t)(b * NHh + head) * Ss + s) * Dd + d);
    }
    cp_wait<0>();
    __syncthreads();

    float acc[2][4][4];
#pragma unroll
    for (int mt = 0; mt < 2; mt++)
#pragma unroll
        for (int nt = 0; nt < 4; nt++)
#pragma unroll
            for (int c = 0; c < 4; c++) acc[mt][nt][c] = 0.f;

    const int akrow = A_TRANS_KROW(lane);
    const int amoff = A_TRANS_MOFF(lane);
    const int bnrow = lane & 7;
    const int bkoff = ((lane >> 3) & 1) * 8;

#pragma unroll
    for (int pass = 0; pass < 2; pass++) {
        const __half* Wp = pass ? Wlo2 : Whi2;
#pragma unroll
        for (int ks = 0; ks < 4; ks++) {
            uint32_t a[2][4], bfr[4][2];
#pragma unroll
            for (int mt = 0; mt < 2; mt++)
                ldsm_x4t(a[mt], Ah + (ks * 16 + akrow) * XST
                                   + wm * 32 + mt * 16 + amoff);
#pragma unroll
            for (int nt = 0; nt < 4; nt++)
                ldsm_x2(bfr[nt], Wp + (wn * 32 + nt * 8 + bnrow) * WST
                                    + ks * 16 + bkoff);
#pragma unroll
            for (int mt = 0; mt < 2; mt++)
#pragma unroll
                for (int nt = 0; nt < 4; nt++)
                    mma_16816(acc[mt][nt], a[mt], bfr[nt]);
        }
    }

#pragma unroll
    for (int mt = 0; mt < 2; mt++) {
        int r0 = wm * 32 + mt * 16 + (lane >> 2);
#pragma unroll
        for (int nt = 0; nt < 4; nt++) {
            int ob = wn * 32 + nt * 8 + (lane & 3) * 2;
#pragma unroll
            for (int c = 0; c < 4; c++) {
                int o  = ob + (c & 1);
                int rr = r0 + (c >> 1) * 8;
                out[((size_t)bs * 64 + o) * HWp + p0 + rr] = acc[mt][nt][c] + b_out[o];
            }
        }
    }
}

// ==================================================================================
extern "C" void kernel_launch(void* const* d_in, const int* in_sizes, int n_in,
                              void* d_out, int out_size) {
    const float* seq   = (const float*)d_in[0];
    const float* w_qkv = (const float*)d_in[1];
    const float* w_out = (const float*)d_in[2];
    const float* b_out = (const float*)d_in[3];
    float* out = (float*)d_out;

    const int qkv_smem = (2 * 64 * XST + 2 * 192 * WST) * (int)sizeof(__half);
    cudaFuncSetAttribute(qkv_mma_kernel, cudaFuncAttributeMaxDynamicSharedMemorySize,
                         qkv_smem);
    cudaFuncSetAttribute(qkv_mma_kernel, cudaFuncAttributePreferredSharedMemoryCarveout,
                         100);
    const int av_smem = (2 * 128 * 64 + 2 * 64 * 128) * (int)sizeof(__half);
    cudaFuncSetAttribute(av_mma_kernel, cudaFuncAttributeMaxDynamicSharedMemorySize,
                         av_smem);
    cudaFuncSetAttribute(av_mma_kernel, cudaFuncAttributePreferredSharedMemoryCarveout,
                         100);

    wsplit_kernel<<<48, 256>>>(w_qkv, w_out);

    dim3 g1(Bb * Ss, 8);
    qkv_mma_kernel<<<g1, 256, qkv_smem>>>(seq);

    dim3 g2(BHh, 4, 4);
    scores_mma_kernel<<<g2, 128>>>();

    softmax_kernel<<<BHh * Ss / 8, 256>>>();

    dim3 g4(BHh, 2, 32);
    av_mma_kernel<<<g4, 256, av_smem>>>();

    dim3 g5(Bb * Ss, 8);
    out_mma_kernel<<<g5, 256>>>(b_out, out);
}